// round 13
// baseline (speedup 1.0000x reference)
#include <cuda_runtime.h>

#define D 64
#define NMAX 100000
#define EMAX 1600000

typedef unsigned long long u64;

// ---------------- scratch (static device globals) ----------------
__device__ float g_h[NMAX * D];    // h (GCN) then h2 (GAT)
__device__ float g_x[NMAX * D];    // GCN output x, then diffused
__device__ float g_as[NMAX];
__device__ float g_ad[NMAX];
__device__ float g_dinv[NMAX];
__device__ int   g_cnt[NMAX];
__device__ int   g_rs[NMAX];
__device__ int   g_cur[NMAX];
__device__ int   g_bsum[256];
__device__ int   g_csrc[EMAX];

// ---------------- helpers ----------------
__device__ __forceinline__ void fma2(u64& acc, u64 a, u64 b) {
    asm("fma.rn.f32x2 %0, %1, %2, %0;" : "+l"(acc) : "l"(a), "l"(b));
}
__device__ __forceinline__ u64 pack2(float lo, float hi) {
    u64 d; asm("mov.b64 %0, {%1, %2};" : "=l"(d) : "f"(lo), "f"(hi)); return d;
}
__device__ __forceinline__ float2 unpack2(u64 v) {
    float2 r; asm("mov.b64 {%0, %1}, %2;" : "=f"(r.x), "=f"(r.y) : "l"(v)); return r;
}
__device__ __forceinline__ float sigmoidf_(float x) { return 1.0f / (1.0f + __expf(-x)); }

#define STRIDE 130  // 128-row tile + 2 pad

// ---------------- CSR build ----------------
__global__ void k_cnt(const int* __restrict__ ei, int E) {
    int i = blockIdx.x * blockDim.x + threadIdx.x;
    int E4 = E >> 2;
    if (i < E4) {
        int4 v = ((const int4*)(ei + E))[i];
        atomicAdd(&g_cnt[v.x], 1);
        atomicAdd(&g_cnt[v.y], 1);
        atomicAdd(&g_cnt[v.z], 1);
        atomicAdd(&g_cnt[v.w], 1);
    } else {
        int t = i - E4;
        if (t < (E & 3)) {
            int e = E4 * 4 + t;
            atomicAdd(&g_cnt[ei[E + e]], 1);
        }
    }
}
__global__ void k_scanA(int n) {
    __shared__ int s[1024];
    int tid = threadIdx.x;
    int i = blockIdx.x * 1024 + tid;
    int v = (i < n) ? g_cnt[i] : 0;
    s[tid] = v; __syncthreads();
    for (int off = 1; off < 1024; off <<= 1) {
        int t = (tid >= off) ? s[tid - off] : 0;
        __syncthreads();
        s[tid] += t; __syncthreads();
    }
    if (i < n) g_rs[i] = s[tid] - v;
    if (tid == 1023) g_bsum[blockIdx.x] = s[1023];
}
__global__ void k_scanC2(int n) {
    __shared__ int sred[32];
    __shared__ int sbase;
    int g = blockIdx.x, tid = threadIdx.x;
    int v = (tid < g) ? g_bsum[tid] : 0;
#pragma unroll
    for (int o = 16; o; o >>= 1) v += __shfl_xor_sync(0xffffffffu, v, o);
    if ((tid & 31) == 0) sred[tid >> 5] = v;
    __syncthreads();
    if (tid < 32) {
        int w = sred[tid];
#pragma unroll
        for (int o = 16; o; o >>= 1) w += __shfl_xor_sync(0xffffffffu, w, o);
        if (tid == 0) sbase = w;
    }
    __syncthreads();
    int i = g * 1024 + tid;
    if (i >= n) return;
    int r = g_rs[i] + sbase;
    g_rs[i] = r;
    g_cur[i] = r;
    g_dinv[i] = rsqrtf((float)g_cnt[i] + 1.0f);  // deg includes self-loop
}
__global__ void k_csr(const int* __restrict__ ei, int E) {
    int i = blockIdx.x * blockDim.x + threadIdx.x;
    int E4 = E >> 2;
    if (i < E4) {
        int4 sv = ((const int4*)ei)[i];
        int4 dv = ((const int4*)(ei + E))[i];
        g_csrc[atomicAdd(&g_cur[dv.x], 1)] = sv.x;
        g_csrc[atomicAdd(&g_cur[dv.y], 1)] = sv.y;
        g_csrc[atomicAdd(&g_cur[dv.z], 1)] = sv.z;
        g_csrc[atomicAdd(&g_cur[dv.w], 1)] = sv.w;
    } else {
        int t = i - E4;
        if (t < (E & 3)) {
            int e = E4 * 4 + t;
            g_csrc[atomicAdd(&g_cur[ei[E + e]], 1)] = ei[e];
        }
    }
}

// ================= fused encoder MLP + GCN weight GEMM =================
__global__ void k_encgemm(const float* __restrict__ ev,
                          const float* __restrict__ W1, const float* __restrict__ b1,
                          const float* __restrict__ W2, const float* __restrict__ b2,
                          const float* __restrict__ gcnW, int n) {
    extern __shared__ float sm[];
    float* evT = sm;                     // 1040
    float* t1T = sm + 1040;              // 8320
    float4* Wb = (float4*)(sm + 9360);   // 1024 float4

    int tid = threadIdx.x;
    int c4 = tid & 15, rp = tid >> 4;
    int row0 = blockIdx.x * 128;

    {
        int rr = tid & 127, q = tid >> 7;
        int gr = row0 + rr;
        float4 v = make_float4(0.f, 0.f, 0.f, 0.f);
        if (gr < n) v = ((const float4*)ev)[gr * 2 + q];
        evT[(q * 4 + 0) * STRIDE + rr] = v.x;
        evT[(q * 4 + 1) * STRIDE + rr] = v.y;
        evT[(q * 4 + 2) * STRIDE + rr] = v.z;
        evT[(q * 4 + 3) * STRIDE + rr] = v.w;
    }
    if (tid < 128) Wb[tid] = ((const float4*)W1)[tid];
    __syncthreads();

    u64 a[4][4];
    {
        float4 b4 = ((const float4*)b1)[c4];
        u64 i0 = pack2(b4.x, b4.x), i1 = pack2(b4.y, b4.y);
        u64 i2 = pack2(b4.z, b4.z), i3 = pack2(b4.w, b4.w);
#pragma unroll
        for (int p = 0; p < 4; p++) { a[p][0] = i0; a[p][1] = i1; a[p][2] = i2; a[p][3] = i3; }
    }
#pragma unroll
    for (int k = 0; k < 8; k++) {
        float4 w = Wb[k * 16 + c4];
        u64 w0 = pack2(w.x, w.x), w1 = pack2(w.y, w.y);
        u64 w2 = pack2(w.z, w.z), w3 = pack2(w.w, w.w);
#pragma unroll
        for (int p = 0; p < 4; p++) {
            u64 x = *(const u64*)&evT[k * STRIDE + 2 * rp + 32 * p];
            fma2(a[p][0], x, w0); fma2(a[p][1], x, w1);
            fma2(a[p][2], x, w2); fma2(a[p][3], x, w3);
        }
    }
#pragma unroll
    for (int p = 0; p < 4; p++)
#pragma unroll
        for (int c = 0; c < 4; c++) {
            float2 v = unpack2(a[p][c]);
            *(u64*)&t1T[(c4 * 4 + c) * STRIDE + 2 * rp + 32 * p] =
                pack2(fmaxf(v.x, 0.f), fmaxf(v.y, 0.f));
        }
    __syncthreads();
    for (int i = tid; i < 1024; i += 256) Wb[i] = ((const float4*)W2)[i];
    __syncthreads();

    {
        float4 b4 = ((const float4*)b2)[c4];
        u64 i0 = pack2(b4.x, b4.x), i1 = pack2(b4.y, b4.y);
        u64 i2 = pack2(b4.z, b4.z), i3 = pack2(b4.w, b4.w);
#pragma unroll
        for (int p = 0; p < 4; p++) { a[p][0] = i0; a[p][1] = i1; a[p][2] = i2; a[p][3] = i3; }
    }
#pragma unroll 4
    for (int k = 0; k < 64; k++) {
        float4 w = Wb[k * 16 + c4];
        u64 w0 = pack2(w.x, w.x), w1 = pack2(w.y, w.y);
        u64 w2 = pack2(w.z, w.z), w3 = pack2(w.w, w.w);
#pragma unroll
        for (int p = 0; p < 4; p++) {
            u64 x = *(const u64*)&t1T[k * STRIDE + 2 * rp + 32 * p];
            fma2(a[p][0], x, w0); fma2(a[p][1], x, w1);
            fma2(a[p][2], x, w2); fma2(a[p][3], x, w3);
        }
    }
    __syncthreads();
#pragma unroll
    for (int p = 0; p < 4; p++)
#pragma unroll
        for (int c = 0; c < 4; c++)
            *(u64*)&t1T[(c4 * 4 + c) * STRIDE + 2 * rp + 32 * p] = a[p][c];
    for (int i = tid; i < 1024; i += 256) Wb[i] = ((const float4*)gcnW)[i];
    __syncthreads();

#pragma unroll
    for (int p = 0; p < 4; p++)
#pragma unroll
        for (int c = 0; c < 4; c++) a[p][c] = 0ull;
#pragma unroll 4
    for (int k = 0; k < 64; k++) {
        float4 w = Wb[k * 16 + c4];
        u64 w0 = pack2(w.x, w.x), w1 = pack2(w.y, w.y);
        u64 w2 = pack2(w.z, w.z), w3 = pack2(w.w, w.w);
#pragma unroll
        for (int p = 0; p < 4; p++) {
            u64 x = *(const u64*)&t1T[k * STRIDE + 2 * rp + 32 * p];
            fma2(a[p][0], x, w0); fma2(a[p][1], x, w1);
            fma2(a[p][2], x, w2); fma2(a[p][3], x, w3);
        }
    }
#pragma unroll
    for (int p = 0; p < 4; p++) {
        int r0 = 2 * rp + 32 * p;
        float2 v0 = unpack2(a[p][0]), v1 = unpack2(a[p][1]);
        float2 v2 = unpack2(a[p][2]), v3 = unpack2(a[p][3]);
        int rowA = row0 + r0, rowB = rowA + 1;
        if (rowA < n) ((float4*)g_h)[rowA * 16 + c4] = make_float4(v0.x, v1.x, v2.x, v3.x);
        if (rowB < n) ((float4*)g_h)[rowB * 16 + c4] = make_float4(v0.y, v1.y, v2.y, v3.y);
    }
}

// ================= GAT weight GEMM + fused att coefficients =================
__global__ void k_gemm_gat(const float* __restrict__ W,
                           const float* __restrict__ att_s, const float* __restrict__ att_d,
                           int n) {
    extern __shared__ float sm[];
    float* xT = sm;                     // 8320
    float4* Ws = (float4*)(sm + 8320);  // 1024 float4

    int tid = threadIdx.x;
    int c4 = tid & 15, rp = tid >> 4;
    int row0 = blockIdx.x * 128;

    for (int i = tid; i < 2048; i += 256) {
        int rr = i & 127, j = i >> 7;
        int gr = row0 + rr;
        float4 v = make_float4(0.f, 0.f, 0.f, 0.f);
        if (gr < n) v = ((const float4*)g_x)[gr * 16 + j];
        xT[(j * 4 + 0) * STRIDE + rr] = v.x;
        xT[(j * 4 + 1) * STRIDE + rr] = v.y;
        xT[(j * 4 + 2) * STRIDE + rr] = v.z;
        xT[(j * 4 + 3) * STRIDE + rr] = v.w;
    }
    for (int i = tid; i < 1024; i += 256) Ws[i] = ((const float4*)W)[i];
    __syncthreads();

    u64 a[4][4];
#pragma unroll
    for (int p = 0; p < 4; p++)
#pragma unroll
        for (int c = 0; c < 4; c++) a[p][c] = 0ull;
#pragma unroll 4
    for (int k = 0; k < 64; k++) {
        float4 w = Ws[k * 16 + c4];
        u64 w0 = pack2(w.x, w.x), w1 = pack2(w.y, w.y);
        u64 w2 = pack2(w.z, w.z), w3 = pack2(w.w, w.w);
#pragma unroll
        for (int p = 0; p < 4; p++) {
            u64 x = *(const u64*)&xT[k * STRIDE + 2 * rp + 32 * p];
            fma2(a[p][0], x, w0); fma2(a[p][1], x, w1);
            fma2(a[p][2], x, w2); fma2(a[p][3], x, w3);
        }
    }

    float4 as4 = ((const float4*)att_s)[c4];
    float4 ad4 = ((const float4*)att_d)[c4];
#pragma unroll
    for (int p = 0; p < 4; p++) {
        int r0 = 2 * rp + 32 * p;
        float2 v0 = unpack2(a[p][0]), v1 = unpack2(a[p][1]);
        float2 v2 = unpack2(a[p][2]), v3 = unpack2(a[p][3]);
        int rowA = row0 + r0, rowB = rowA + 1;
        if (rowA < n) ((float4*)g_h)[rowA * 16 + c4] = make_float4(v0.x, v1.x, v2.x, v3.x);
        if (rowB < n) ((float4*)g_h)[rowB * 16 + c4] = make_float4(v0.y, v1.y, v2.y, v3.y);

        u64 ps = 0ull, pd = 0ull;
        fma2(ps, a[p][0], pack2(as4.x, as4.x)); fma2(pd, a[p][0], pack2(ad4.x, ad4.x));
        fma2(ps, a[p][1], pack2(as4.y, as4.y)); fma2(pd, a[p][1], pack2(ad4.y, ad4.y));
        fma2(ps, a[p][2], pack2(as4.z, as4.z)); fma2(pd, a[p][2], pack2(ad4.z, ad4.z));
        fma2(ps, a[p][3], pack2(as4.w, as4.w)); fma2(pd, a[p][3], pack2(ad4.w, ad4.w));
#pragma unroll
        for (int o = 8; o; o >>= 1) {
            u64 tps = __shfl_xor_sync(0xffffffffu, ps, o);
            u64 tpd = __shfl_xor_sync(0xffffffffu, pd, o);
            float2 va = unpack2(ps), vb = unpack2(tps);
            ps = pack2(va.x + vb.x, va.y + vb.y);
            va = unpack2(pd); vb = unpack2(tpd);
            pd = pack2(va.x + vb.x, va.y + vb.y);
        }
        if (c4 == 0) {
            float2 vs = unpack2(ps), vd = unpack2(pd);
            if (rowA < n) { g_as[rowA] = vs.x; g_ad[rowA] = vd.x; }
            if (rowB < n) { g_as[rowB] = vs.y; g_ad[rowB] = vd.y; }
        }
    }
}

// ---------------- GCN pull aggregation (warp/node) ----------------
__global__ void k_gcn_agg(const float* __restrict__ b, int n) {
    int gt = blockIdx.x * blockDim.x + threadIdx.x;
    int d = gt >> 5, lane = gt & 31;
    if (d >= n) return;
    const float2* H2 = (const float2*)g_h;
    float dinv_d = g_dinv[d];
    float2 hv = H2[d * 32 + lane];
    float sn = dinv_d * dinv_d;
    float ax = hv.x * sn, ay = hv.y * sn;
    int beg = g_rs[d], cnt = g_cnt[d];
    for (int c0 = 0; c0 < cnt; c0 += 32) {
        int idx = c0 + lane;
        int s = 0; float nm = 0.f;
        if (idx < cnt) { s = __ldg(&g_csrc[beg + idx]); nm = g_dinv[s] * dinv_d; }
        int m = min(32, cnt - c0);
        int j = 0;
        for (; j + 4 <= m; j += 4) {
            int s0 = __shfl_sync(0xffffffffu, s, j);
            int s1 = __shfl_sync(0xffffffffu, s, j + 1);
            int s2 = __shfl_sync(0xffffffffu, s, j + 2);
            int s3 = __shfl_sync(0xffffffffu, s, j + 3);
            float n0 = __shfl_sync(0xffffffffu, nm, j);
            float n1 = __shfl_sync(0xffffffffu, nm, j + 1);
            float n2 = __shfl_sync(0xffffffffu, nm, j + 2);
            float n3 = __shfl_sync(0xffffffffu, nm, j + 3);
            float2 v0 = H2[s0 * 32 + lane];
            float2 v1 = H2[s1 * 32 + lane];
            float2 v2 = H2[s2 * 32 + lane];
            float2 v3 = H2[s3 * 32 + lane];
            ax = fmaf(n0, v0.x, ax); ay = fmaf(n0, v0.y, ay);
            ax = fmaf(n1, v1.x, ax); ay = fmaf(n1, v1.y, ay);
            ax = fmaf(n2, v2.x, ax); ay = fmaf(n2, v2.y, ay);
            ax = fmaf(n3, v3.x, ax); ay = fmaf(n3, v3.y, ay);
        }
        for (; j < m; j++) {
            int sj = __shfl_sync(0xffffffffu, s, j);
            float nj = __shfl_sync(0xffffffffu, nm, j);
            float2 v = H2[sj * 32 + lane];
            ax = fmaf(nj, v.x, ax); ay = fmaf(nj, v.y, ay);
        }
    }
    float2 bb = ((const float2*)b)[lane];
    float2 o;
    o.x = fmaxf(ax + bb.x, 0.f);
    o.y = fmaxf(ay + bb.y, 0.f);
    ((float2*)g_x)[d * 32 + lane] = o;
}

// ---------------- GAT pull aggregation (warp/node) ----------------
__global__ void k_gat_agg(const float* __restrict__ b, int n) {
    int gt = blockIdx.x * blockDim.x + threadIdx.x;
    int d = gt >> 5, lane = gt & 31;
    if (d >= n) return;
    const float2* H2 = (const float2*)g_h;
    float ad_d = g_ad[d];
    float e0 = g_as[d] + ad_d;
    float l0 = e0 > 0.f ? e0 : 0.2f * e0;
    float wself = __expf(l0);
    float2 hd = H2[d * 32 + lane];
    float ax = wself * hd.x, ay = wself * hd.y;
    float zp = (lane == 0) ? wself : 0.f;
    int beg = g_rs[d], cnt = g_cnt[d];
    for (int c0 = 0; c0 < cnt; c0 += 32) {
        int idx = c0 + lane;
        int s = 0; float w = 0.f;
        if (idx < cnt) {
            s = __ldg(&g_csrc[beg + idx]);
            float ev = g_as[s] + ad_d;
            float lr = ev > 0.f ? ev : 0.2f * ev;
            w = __expf(lr);
        }
        zp += w;
        int m = min(32, cnt - c0);
        int j = 0;
        for (; j + 4 <= m; j += 4) {
            int s0 = __shfl_sync(0xffffffffu, s, j);
            int s1 = __shfl_sync(0xffffffffu, s, j + 1);
            int s2 = __shfl_sync(0xffffffffu, s, j + 2);
            int s3 = __shfl_sync(0xffffffffu, s, j + 3);
            float w0 = __shfl_sync(0xffffffffu, w, j);
            float w1 = __shfl_sync(0xffffffffu, w, j + 1);
            float w2 = __shfl_sync(0xffffffffu, w, j + 2);
            float w3 = __shfl_sync(0xffffffffu, w, j + 3);
            float2 v0 = H2[s0 * 32 + lane];
            float2 v1 = H2[s1 * 32 + lane];
            float2 v2 = H2[s2 * 32 + lane];
            float2 v3 = H2[s3 * 32 + lane];
            ax = fmaf(w0, v0.x, ax); ay = fmaf(w0, v0.y, ay);
            ax = fmaf(w1, v1.x, ax); ay = fmaf(w1, v1.y, ay);
            ax = fmaf(w2, v2.x, ax); ay = fmaf(w2, v2.y, ay);
            ax = fmaf(w3, v3.x, ax); ay = fmaf(w3, v3.y, ay);
        }
        for (; j < m; j++) {
            int sj = __shfl_sync(0xffffffffu, s, j);
            float wj = __shfl_sync(0xffffffffu, w, j);
            float2 v = H2[sj * 32 + lane];
            ax = fmaf(wj, v.x, ax); ay = fmaf(wj, v.y, ay);
        }
    }
#pragma unroll
    for (int o = 16; o; o >>= 1) zp += __shfl_xor_sync(0xffffffffu, zp, o);
    float inv = 1.0f / zp;
    float2 bb = ((const float2*)b)[lane];
    float2 o2;
    o2.x = fmaxf(fmaf(ax, inv, bb.x), 0.f);
    o2.y = fmaxf(fmaf(ay, inv, bb.y), 0.f);
    ((float2*)g_x)[d * 32 + lane] = o2;
}

// ======= fused gate + residual + speed head (merged gate/res1 k-loop) =======
// smem: fusT[128*130]=16640 f | Wb f4[4096] = gate_W(0..2047) | res_W1(2048..4095)
__global__ void __launch_bounds__(256, 1)
k_final(const float* __restrict__ H,
        const float* __restrict__ gate_W, const float* __restrict__ gate_b,
        const float* __restrict__ res_W1, const float* __restrict__ res_b1,
        const float* __restrict__ res_W2, const float* __restrict__ res_b2,
        const float* __restrict__ sp_W1, const float* __restrict__ sp_b1,
        const float* __restrict__ sp_W2, const float* __restrict__ sp_b2,
        float* __restrict__ delta_out, float* __restrict__ hf_out,
        float* __restrict__ pred_out, int n) {
    extern __shared__ float sm[];
    float* fusT = sm;                        // 16640 floats
    float4* Wb  = (float4*)(sm + 16640);     // 4096 float4

    int tid = threadIdx.x;
    int c4 = tid & 15, rp = tid >> 4;
    int row0 = blockIdx.x * 128;

    for (int i = tid; i < 4096; i += 256) {
        int rr = i & 127, j = i >> 7;
        int gr = row0 + rr;
        float4 v = make_float4(0.f, 0.f, 0.f, 0.f);
        if (gr < n) v = (j < 16) ? ((const float4*)H)[gr * 16 + j]
                                 : ((const float4*)g_x)[gr * 16 + (j - 16)];
        fusT[(j * 4 + 0) * STRIDE + rr] = v.x;
        fusT[(j * 4 + 1) * STRIDE + rr] = v.y;
        fusT[(j * 4 + 2) * STRIDE + rr] = v.z;
        fusT[(j * 4 + 3) * STRIDE + rr] = v.w;
    }
    for (int i = tid; i < 2048; i += 256) Wb[i] = ((const float4*)gate_W)[i];
    for (int i = tid; i < 2048; i += 256) Wb[2048 + i] = ((const float4*)res_W1)[i];
    __syncthreads();

    // ---- merged gate + res1 GEMMs: one x stream, two accumulator sets ----
    u64 ga[4][4], ra[4][4];
    {
        float4 b4 = ((const float4*)gate_b)[c4];
        u64 i0 = pack2(b4.x, b4.x), i1 = pack2(b4.y, b4.y);
        u64 i2 = pack2(b4.z, b4.z), i3 = pack2(b4.w, b4.w);
#pragma unroll
        for (int p = 0; p < 4; p++) { ga[p][0] = i0; ga[p][1] = i1; ga[p][2] = i2; ga[p][3] = i3; }
        b4 = ((const float4*)res_b1)[c4];
        i0 = pack2(b4.x, b4.x); i1 = pack2(b4.y, b4.y);
        i2 = pack2(b4.z, b4.z); i3 = pack2(b4.w, b4.w);
#pragma unroll
        for (int p = 0; p < 4; p++) { ra[p][0] = i0; ra[p][1] = i1; ra[p][2] = i2; ra[p][3] = i3; }
    }
#pragma unroll 2
    for (int k = 0; k < 128; k++) {
        float4 wg = Wb[k * 16 + c4];
        float4 wr = Wb[2048 + k * 16 + c4];
        u64 g0 = pack2(wg.x, wg.x), g1 = pack2(wg.y, wg.y);
        u64 g2 = pack2(wg.z, wg.z), g3 = pack2(wg.w, wg.w);
        u64 r0_ = pack2(wr.x, wr.x), r1_ = pack2(wr.y, wr.y);
        u64 r2_ = pack2(wr.z, wr.z), r3_ = pack2(wr.w, wr.w);
#pragma unroll
        for (int p = 0; p < 4; p++) {
            u64 x = *(const u64*)&fusT[k * STRIDE + 2 * rp + 32 * p];
            fma2(ga[p][0], x, g0); fma2(ga[p][1], x, g1);
            fma2(ga[p][2], x, g2); fma2(ga[p][3], x, g3);
            fma2(ra[p][0], x, r0_); fma2(ra[p][1], x, r1_);
            fma2(ra[p][2], x, r2_); fma2(ra[p][3], x, r3_);
        }
    }
    __syncthreads();  // diffused cols fully consumed
    // write t1 = relu(res1) into fusT cols 64..127
#pragma unroll
    for (int p = 0; p < 4; p++)
#pragma unroll
        for (int c = 0; c < 4; c++) {
            float2 v = unpack2(ra[p][c]);
            *(u64*)&fusT[(64 + c4 * 4 + c) * STRIDE + 2 * rp + 32 * p] =
                pack2(fmaxf(v.x, 0.f), fmaxf(v.y, 0.f));
        }
    for (int i = tid; i < 1024; i += 256) Wb[i] = ((const float4*)res_W2)[i];
    __syncthreads();

    // ---- res layer 2 ----
    {
        float4 b4 = ((const float4*)res_b2)[c4];
        u64 i0 = pack2(b4.x, b4.x), i1 = pack2(b4.y, b4.y);
        u64 i2 = pack2(b4.z, b4.z), i3 = pack2(b4.w, b4.w);
#pragma unroll
        for (int p = 0; p < 4; p++) { ra[p][0] = i0; ra[p][1] = i1; ra[p][2] = i2; ra[p][3] = i3; }
    }
#pragma unroll 4
    for (int k = 0; k < 64; k++) {
        float4 w = Wb[k * 16 + c4];
        u64 w0 = pack2(w.x, w.x), w1 = pack2(w.y, w.y);
        u64 w2 = pack2(w.z, w.z), w3 = pack2(w.w, w.w);
#pragma unroll
        for (int p = 0; p < 4; p++) {
            u64 x = *(const u64*)&fusT[(64 + k) * STRIDE + 2 * rp + 32 * p];
            fma2(ra[p][0], x, w0); fma2(ra[p][1], x, w1);
            fma2(ra[p][2], x, w2); fma2(ra[p][3], x, w3);
        }
    }
    __syncthreads();

    // ---- delta / H_final ----
#pragma unroll
    for (int p = 0; p < 4; p++) {
        int r0 = 2 * rp + 32 * p;
        float d_[4][2], hf_[4][2];
#pragma unroll
        for (int c = 0; c < 4; c++) {
            float2 rv = unpack2(ra[p][c]);
            float2 gvv = unpack2(ga[p][c]);
            float2 hv = unpack2(*(const u64*)&fusT[(c4 * 4 + c) * STRIDE + r0]);
            d_[c][0] = sigmoidf_(gvv.x) * rv.x;
            d_[c][1] = sigmoidf_(gvv.y) * rv.y;
            hf_[c][0] = hv.x + d_[c][0];
            hf_[c][1] = hv.y + d_[c][1];
            *(u64*)&fusT[(64 + c4 * 4 + c) * STRIDE + r0] = pack2(hf_[c][0], hf_[c][1]);
        }
#pragma unroll
        for (int e = 0; e < 2; e++) {
            int row = row0 + r0 + e;
            if (row < n) {
                ((float4*)delta_out)[row * 16 + c4] =
                    make_float4(d_[0][e], d_[1][e], d_[2][e], d_[3][e]);
                ((float4*)hf_out)[row * 16 + c4] =
                    make_float4(hf_[0][e], hf_[1][e], hf_[2][e], hf_[3][e]);
            }
        }
    }
    for (int i = tid; i < 512; i += 256) Wb[i] = ((const float4*)sp_W1)[i];
    __syncthreads();

    float* tb = sm;  // reuse H region (cols 0..32): 128 rows x stride 33
    {
        u64 sa[4][2];
        float2 bb = ((const float2*)sp_b1)[c4];
        u64 i0 = pack2(bb.x, bb.x), i1 = pack2(bb.y, bb.y);
#pragma unroll
        for (int p = 0; p < 4; p++) { sa[p][0] = i0; sa[p][1] = i1; }
#pragma unroll 4
        for (int k = 0; k < 64; k++) {
            float2 wv = ((const float2*)Wb)[k * 16 + c4];
            u64 w0 = pack2(wv.x, wv.x), w1 = pack2(wv.y, wv.y);
#pragma unroll
            for (int p = 0; p < 4; p++) {
                u64 x = *(const u64*)&fusT[(64 + k) * STRIDE + 2 * rp + 32 * p];
                fma2(sa[p][0], x, w0); fma2(sa[p][1], x, w1);
            }
        }
        __syncthreads();
#pragma unroll
        for (int p = 0; p < 4; p++) {
            int r0 = 2 * rp + 32 * p;
#pragma unroll
            for (int c = 0; c < 2; c++) {
                float2 v = unpack2(sa[p][c]);
                tb[(r0 + 0) * 33 + c4 * 2 + c] = fmaxf(v.x, 0.f);
                tb[(r0 + 1) * 33 + c4 * 2 + c] = fmaxf(v.y, 0.f);
            }
        }
    }
    __syncthreads();
    if (tid < 128) {
        int gr = row0 + tid;
        if (gr < n) {
            float acc = sp_b2[0];
#pragma unroll
            for (int k = 0; k < 32; k++) acc = fmaf(tb[tid * 33 + k], __ldg(&sp_W2[k]), acc);
            pred_out[gr] = acc;
        }
    }
}

// ---------------- launch ----------------
extern "C" void kernel_launch(void* const* d_in, const int* in_sizes, int n_in,
                              void* d_out, int out_size) {
    const float* H      = (const float*)d_in[0];
    const float* ev     = (const float*)d_in[1];
    const int*   ei     = (const int*)d_in[2];
    const float* enc_W1 = (const float*)d_in[3];
    const float* enc_b1 = (const float*)d_in[4];
    const float* enc_W2 = (const float*)d_in[5];
    const float* enc_b2 = (const float*)d_in[6];
    const float* gcn_W  = (const float*)d_in[7];
    const float* gcn_b  = (const float*)d_in[8];
    const float* gat_W  = (const float*)d_in[9];
    const float* att_s  = (const float*)d_in[10];
    const float* att_d  = (const float*)d_in[11];
    const float* gat_b  = (const float*)d_in[12];
    const float* gate_W = (const float*)d_in[13];
    const float* gate_b = (const float*)d_in[14];
    const float* res_W1 = (const float*)d_in[15];
    const float* res_b1 = (const float*)d_in[16];
    const float* res_W2 = (const float*)d_in[17];
    const float* res_b2 = (const float*)d_in[18];
    const float* sp_W1  = (const float*)d_in[19];
    const float* sp_b1  = (const float*)d_in[20];
    const float* sp_W2  = (const float*)d_in[21];
    const float* sp_b2  = (const float*)d_in[22];

    int n = in_sizes[0] / 64;
    int E = in_sizes[2] / 2;

    float* delta = (float*)d_out;
    float* hf    = delta + (size_t)n * 64;
    float* pred  = hf + (size_t)n * 64;

    int nb128  = (n + 127) / 128;
    int nb1024 = (n + 1023) / 1024;
    int nbW    = (n * 32 + 255) / 256;
    int E4     = E >> 2;
    int nbE4   = (E4 + (E & 3) + 255) / 256;

    const int ENC_SMEM = (1040 + 8320) * 4 + 1024 * 16;  // 53824
    const int GAT_SMEM = 8320 * 4 + 1024 * 16;           // 49664
    const int FIN_SMEM = 16640 * 4 + 4096 * 16;          // 132096

    static cudaStream_t s2 = nullptr;
    static cudaEvent_t evFork = nullptr, evJoin = nullptr;
    static void* cnt_ptr = nullptr;
    if (!s2) {
        cudaStreamCreate(&s2);
        cudaEventCreateWithFlags(&evFork, cudaEventDisableTiming);
        cudaEventCreateWithFlags(&evJoin, cudaEventDisableTiming);
        cudaGetSymbolAddress(&cnt_ptr, g_cnt);
        cudaFuncSetAttribute(k_encgemm, cudaFuncAttributeMaxDynamicSharedMemorySize, ENC_SMEM);
        cudaFuncSetAttribute(k_gemm_gat, cudaFuncAttributeMaxDynamicSharedMemorySize, GAT_SMEM);
        cudaFuncSetAttribute(k_final, cudaFuncAttributeMaxDynamicSharedMemorySize, FIN_SMEM);
    }

    // fork: encoder GEMM chain on s2, CSR build on main (default) stream
    cudaEventRecord(evFork, 0);
    cudaStreamWaitEvent(s2, evFork, 0);
    k_encgemm<<<nb128, 256, ENC_SMEM, s2>>>(ev, enc_W1, enc_b1, enc_W2, enc_b2, gcn_W, n);
    cudaEventRecord(evJoin, s2);

    cudaMemsetAsync(cnt_ptr, 0, (size_t)n * sizeof(int), 0);
    k_cnt<<<nbE4, 256>>>(ei, E);
    k_scanA<<<nb1024, 1024>>>(n);
    k_scanC2<<<nb1024, 1024>>>(n);
    k_csr<<<nbE4, 256>>>(ei, E);

    // join: aggregation needs both h (s2) and CSR (main)
    cudaStreamWaitEvent(0, evJoin, 0);
    k_gcn_agg<<<nbW, 256>>>(gcn_b, n);
    k_gemm_gat<<<nb128, 256, GAT_SMEM>>>(gat_W, att_s, att_d, n);
    k_gat_agg<<<nbW, 256>>>(gat_b, n);
    k_final<<<nb128, 256, FIN_SMEM>>>(H, gate_W, gate_b, res_W1, res_b1, res_W2, res_b2,
                                      sp_W1, sp_b1, sp_W2, sp_b2, delta, hf, pred, n);
}

// round 15
// speedup vs baseline: 1.6935x; 1.6935x over previous
#include <cuda_runtime.h>

#define D 64
#define NMAX 100000
#define EMAX 1600000

typedef unsigned long long u64;

// ---------------- scratch (static device globals) ----------------
__device__ float g_h[NMAX * D];    // h (GCN) then h2 (GAT)
__device__ float g_x[NMAX * D];    // GCN output x, then diffused
__device__ float g_as[NMAX];
__device__ float g_ad[NMAX];
__device__ float g_dinv[NMAX];
__device__ int   g_cnt[NMAX];
__device__ int   g_rs[NMAX];
__device__ int   g_cur[NMAX];
__device__ int   g_bsum[256];
__device__ int   g_csrc[EMAX];

// ---------------- helpers ----------------
__device__ __forceinline__ void fma2(u64& acc, u64 a, u64 b) {
    asm("fma.rn.f32x2 %0, %1, %2, %0;" : "+l"(acc) : "l"(a), "l"(b));
}
__device__ __forceinline__ u64 pack2(float lo, float hi) {
    u64 d; asm("mov.b64 %0, {%1, %2};" : "=l"(d) : "f"(lo), "f"(hi)); return d;
}
__device__ __forceinline__ float2 unpack2(u64 v) {
    float2 r; asm("mov.b64 {%0, %1}, %2;" : "=f"(r.x), "=f"(r.y) : "l"(v)); return r;
}
__device__ __forceinline__ float sigmoidf_(float x) { return 1.0f / (1.0f + __expf(-x)); }

#define STRIDE 130  // 128-row tile + 2 pad

// ---------------- CSR build ----------------
__global__ void k_cnt(const int* __restrict__ ei, int E) {
    int i = blockIdx.x * blockDim.x + threadIdx.x;
    int E4 = E >> 2;
    if (i < E4) {
        int4 v = ((const int4*)(ei + E))[i];
        atomicAdd(&g_cnt[v.x], 1);
        atomicAdd(&g_cnt[v.y], 1);
        atomicAdd(&g_cnt[v.z], 1);
        atomicAdd(&g_cnt[v.w], 1);
    } else {
        int t = i - E4;
        if (t < (E & 3)) {
            int e = E4 * 4 + t;
            atomicAdd(&g_cnt[ei[E + e]], 1);
        }
    }
}
__global__ void k_scanA(int n) {
    __shared__ int s[1024];
    int tid = threadIdx.x;
    int i = blockIdx.x * 1024 + tid;
    int v = (i < n) ? g_cnt[i] : 0;
    s[tid] = v; __syncthreads();
    for (int off = 1; off < 1024; off <<= 1) {
        int t = (tid >= off) ? s[tid - off] : 0;
        __syncthreads();
        s[tid] += t; __syncthreads();
    }
    if (i < n) g_rs[i] = s[tid] - v;
    if (tid == 1023) g_bsum[blockIdx.x] = s[1023];
}
__global__ void k_scanC2(int n) {
    __shared__ int sred[32];
    __shared__ int sbase;
    int g = blockIdx.x, tid = threadIdx.x;
    int v = (tid < g) ? g_bsum[tid] : 0;
#pragma unroll
    for (int o = 16; o; o >>= 1) v += __shfl_xor_sync(0xffffffffu, v, o);
    if ((tid & 31) == 0) sred[tid >> 5] = v;
    __syncthreads();
    if (tid < 32) {
        int w = sred[tid];
#pragma unroll
        for (int o = 16; o; o >>= 1) w += __shfl_xor_sync(0xffffffffu, w, o);
        if (tid == 0) sbase = w;
    }
    __syncthreads();
    int i = g * 1024 + tid;
    if (i >= n) return;
    int r = g_rs[i] + sbase;
    g_rs[i] = r;
    g_cur[i] = r;
    g_dinv[i] = rsqrtf((float)g_cnt[i] + 1.0f);  // deg includes self-loop
}
__global__ void k_csr(const int* __restrict__ ei, int E) {
    int i = blockIdx.x * blockDim.x + threadIdx.x;
    int E4 = E >> 2;
    if (i < E4) {
        int4 sv = ((const int4*)ei)[i];
        int4 dv = ((const int4*)(ei + E))[i];
        g_csrc[atomicAdd(&g_cur[dv.x], 1)] = sv.x;
        g_csrc[atomicAdd(&g_cur[dv.y], 1)] = sv.y;
        g_csrc[atomicAdd(&g_cur[dv.z], 1)] = sv.z;
        g_csrc[atomicAdd(&g_cur[dv.w], 1)] = sv.w;
    } else {
        int t = i - E4;
        if (t < (E & 3)) {
            int e = E4 * 4 + t;
            g_csrc[atomicAdd(&g_cur[ei[E + e]], 1)] = ei[e];
        }
    }
}

// ================= fused encoder MLP + GCN weight GEMM =================
__global__ void k_encgemm(const float* __restrict__ ev,
                          const float* __restrict__ W1, const float* __restrict__ b1,
                          const float* __restrict__ W2, const float* __restrict__ b2,
                          const float* __restrict__ gcnW, int n) {
    extern __shared__ float sm[];
    float* evT = sm;                     // 1040
    float* t1T = sm + 1040;              // 8320
    float4* Wb = (float4*)(sm + 9360);   // 1024 float4

    int tid = threadIdx.x;
    int c4 = tid & 15, rp = tid >> 4;
    int row0 = blockIdx.x * 128;

    {
        int rr = tid & 127, q = tid >> 7;
        int gr = row0 + rr;
        float4 v = make_float4(0.f, 0.f, 0.f, 0.f);
        if (gr < n) v = ((const float4*)ev)[gr * 2 + q];
        evT[(q * 4 + 0) * STRIDE + rr] = v.x;
        evT[(q * 4 + 1) * STRIDE + rr] = v.y;
        evT[(q * 4 + 2) * STRIDE + rr] = v.z;
        evT[(q * 4 + 3) * STRIDE + rr] = v.w;
    }
    if (tid < 128) Wb[tid] = ((const float4*)W1)[tid];
    __syncthreads();

    u64 a[4][4];
    {
        float4 b4 = ((const float4*)b1)[c4];
        u64 i0 = pack2(b4.x, b4.x), i1 = pack2(b4.y, b4.y);
        u64 i2 = pack2(b4.z, b4.z), i3 = pack2(b4.w, b4.w);
#pragma unroll
        for (int p = 0; p < 4; p++) { a[p][0] = i0; a[p][1] = i1; a[p][2] = i2; a[p][3] = i3; }
    }
#pragma unroll
    for (int k = 0; k < 8; k++) {
        float4 w = Wb[k * 16 + c4];
        u64 w0 = pack2(w.x, w.x), w1 = pack2(w.y, w.y);
        u64 w2 = pack2(w.z, w.z), w3 = pack2(w.w, w.w);
#pragma unroll
        for (int p = 0; p < 4; p++) {
            u64 x = *(const u64*)&evT[k * STRIDE + 2 * rp + 32 * p];
            fma2(a[p][0], x, w0); fma2(a[p][1], x, w1);
            fma2(a[p][2], x, w2); fma2(a[p][3], x, w3);
        }
    }
#pragma unroll
    for (int p = 0; p < 4; p++)
#pragma unroll
        for (int c = 0; c < 4; c++) {
            float2 v = unpack2(a[p][c]);
            *(u64*)&t1T[(c4 * 4 + c) * STRIDE + 2 * rp + 32 * p] =
                pack2(fmaxf(v.x, 0.f), fmaxf(v.y, 0.f));
        }
    __syncthreads();
    for (int i = tid; i < 1024; i += 256) Wb[i] = ((const float4*)W2)[i];
    __syncthreads();

    {
        float4 b4 = ((const float4*)b2)[c4];
        u64 i0 = pack2(b4.x, b4.x), i1 = pack2(b4.y, b4.y);
        u64 i2 = pack2(b4.z, b4.z), i3 = pack2(b4.w, b4.w);
#pragma unroll
        for (int p = 0; p < 4; p++) { a[p][0] = i0; a[p][1] = i1; a[p][2] = i2; a[p][3] = i3; }
    }
#pragma unroll 4
    for (int k = 0; k < 64; k++) {
        float4 w = Wb[k * 16 + c4];
        u64 w0 = pack2(w.x, w.x), w1 = pack2(w.y, w.y);
        u64 w2 = pack2(w.z, w.z), w3 = pack2(w.w, w.w);
#pragma unroll
        for (int p = 0; p < 4; p++) {
            u64 x = *(const u64*)&t1T[k * STRIDE + 2 * rp + 32 * p];
            fma2(a[p][0], x, w0); fma2(a[p][1], x, w1);
            fma2(a[p][2], x, w2); fma2(a[p][3], x, w3);
        }
    }
    __syncthreads();
#pragma unroll
    for (int p = 0; p < 4; p++)
#pragma unroll
        for (int c = 0; c < 4; c++)
            *(u64*)&t1T[(c4 * 4 + c) * STRIDE + 2 * rp + 32 * p] = a[p][c];
    for (int i = tid; i < 1024; i += 256) Wb[i] = ((const float4*)gcnW)[i];
    __syncthreads();

#pragma unroll
    for (int p = 0; p < 4; p++)
#pragma unroll
        for (int c = 0; c < 4; c++) a[p][c] = 0ull;
#pragma unroll 4
    for (int k = 0; k < 64; k++) {
        float4 w = Wb[k * 16 + c4];
        u64 w0 = pack2(w.x, w.x), w1 = pack2(w.y, w.y);
        u64 w2 = pack2(w.z, w.z), w3 = pack2(w.w, w.w);
#pragma unroll
        for (int p = 0; p < 4; p++) {
            u64 x = *(const u64*)&t1T[k * STRIDE + 2 * rp + 32 * p];
            fma2(a[p][0], x, w0); fma2(a[p][1], x, w1);
            fma2(a[p][2], x, w2); fma2(a[p][3], x, w3);
        }
    }
#pragma unroll
    for (int p = 0; p < 4; p++) {
        int r0 = 2 * rp + 32 * p;
        float2 v0 = unpack2(a[p][0]), v1 = unpack2(a[p][1]);
        float2 v2 = unpack2(a[p][2]), v3 = unpack2(a[p][3]);
        int rowA = row0 + r0, rowB = rowA + 1;
        if (rowA < n) ((float4*)g_h)[rowA * 16 + c4] = make_float4(v0.x, v1.x, v2.x, v3.x);
        if (rowB < n) ((float4*)g_h)[rowB * 16 + c4] = make_float4(v0.y, v1.y, v2.y, v3.y);
    }
}

// ================= GAT weight GEMM + fused att coefficients =================
__global__ void k_gemm_gat(const float* __restrict__ W,
                           const float* __restrict__ att_s, const float* __restrict__ att_d,
                           int n) {
    extern __shared__ float sm[];
    float* xT = sm;                     // 8320
    float4* Ws = (float4*)(sm + 8320);  // 1024 float4

    int tid = threadIdx.x;
    int c4 = tid & 15, rp = tid >> 4;
    int row0 = blockIdx.x * 128;

    for (int i = tid; i < 2048; i += 256) {
        int rr = i & 127, j = i >> 7;
        int gr = row0 + rr;
        float4 v = make_float4(0.f, 0.f, 0.f, 0.f);
        if (gr < n) v = ((const float4*)g_x)[gr * 16 + j];
        xT[(j * 4 + 0) * STRIDE + rr] = v.x;
        xT[(j * 4 + 1) * STRIDE + rr] = v.y;
        xT[(j * 4 + 2) * STRIDE + rr] = v.z;
        xT[(j * 4 + 3) * STRIDE + rr] = v.w;
    }
    for (int i = tid; i < 1024; i += 256) Ws[i] = ((const float4*)W)[i];
    __syncthreads();

    u64 a[4][4];
#pragma unroll
    for (int p = 0; p < 4; p++)
#pragma unroll
        for (int c = 0; c < 4; c++) a[p][c] = 0ull;
#pragma unroll 4
    for (int k = 0; k < 64; k++) {
        float4 w = Ws[k * 16 + c4];
        u64 w0 = pack2(w.x, w.x), w1 = pack2(w.y, w.y);
        u64 w2 = pack2(w.z, w.z), w3 = pack2(w.w, w.w);
#pragma unroll
        for (int p = 0; p < 4; p++) {
            u64 x = *(const u64*)&xT[k * STRIDE + 2 * rp + 32 * p];
            fma2(a[p][0], x, w0); fma2(a[p][1], x, w1);
            fma2(a[p][2], x, w2); fma2(a[p][3], x, w3);
        }
    }

    float4 as4 = ((const float4*)att_s)[c4];
    float4 ad4 = ((const float4*)att_d)[c4];
#pragma unroll
    for (int p = 0; p < 4; p++) {
        int r0 = 2 * rp + 32 * p;
        float2 v0 = unpack2(a[p][0]), v1 = unpack2(a[p][1]);
        float2 v2 = unpack2(a[p][2]), v3 = unpack2(a[p][3]);
        int rowA = row0 + r0, rowB = rowA + 1;
        if (rowA < n) ((float4*)g_h)[rowA * 16 + c4] = make_float4(v0.x, v1.x, v2.x, v3.x);
        if (rowB < n) ((float4*)g_h)[rowB * 16 + c4] = make_float4(v0.y, v1.y, v2.y, v3.y);

        u64 ps = 0ull, pd = 0ull;
        fma2(ps, a[p][0], pack2(as4.x, as4.x)); fma2(pd, a[p][0], pack2(ad4.x, ad4.x));
        fma2(ps, a[p][1], pack2(as4.y, as4.y)); fma2(pd, a[p][1], pack2(ad4.y, ad4.y));
        fma2(ps, a[p][2], pack2(as4.z, as4.z)); fma2(pd, a[p][2], pack2(ad4.z, ad4.z));
        fma2(ps, a[p][3], pack2(as4.w, as4.w)); fma2(pd, a[p][3], pack2(ad4.w, ad4.w));
#pragma unroll
        for (int o = 8; o; o >>= 1) {
            u64 tps = __shfl_xor_sync(0xffffffffu, ps, o);
            u64 tpd = __shfl_xor_sync(0xffffffffu, pd, o);
            float2 va = unpack2(ps), vb = unpack2(tps);
            ps = pack2(va.x + vb.x, va.y + vb.y);
            va = unpack2(pd); vb = unpack2(tpd);
            pd = pack2(va.x + vb.x, va.y + vb.y);
        }
        if (c4 == 0) {
            float2 vs = unpack2(ps), vd = unpack2(pd);
            if (rowA < n) { g_as[rowA] = vs.x; g_ad[rowA] = vd.x; }
            if (rowB < n) { g_as[rowB] = vs.y; g_ad[rowB] = vd.y; }
        }
    }
}

// ---------------- GCN pull aggregation (warp/node) ----------------
__global__ void k_gcn_agg(const float* __restrict__ b, int n) {
    int gt = blockIdx.x * blockDim.x + threadIdx.x;
    int d = gt >> 5, lane = gt & 31;
    if (d >= n) return;
    const float2* H2 = (const float2*)g_h;
    float dinv_d = g_dinv[d];
    float2 hv = H2[d * 32 + lane];
    float sn = dinv_d * dinv_d;
    float ax = hv.x * sn, ay = hv.y * sn;
    int beg = g_rs[d], cnt = g_cnt[d];
    for (int c0 = 0; c0 < cnt; c0 += 32) {
        int idx = c0 + lane;
        int s = 0; float nm = 0.f;
        if (idx < cnt) { s = __ldg(&g_csrc[beg + idx]); nm = g_dinv[s] * dinv_d; }
        int m = min(32, cnt - c0);
        int j = 0;
        for (; j + 4 <= m; j += 4) {
            int s0 = __shfl_sync(0xffffffffu, s, j);
            int s1 = __shfl_sync(0xffffffffu, s, j + 1);
            int s2 = __shfl_sync(0xffffffffu, s, j + 2);
            int s3 = __shfl_sync(0xffffffffu, s, j + 3);
            float n0 = __shfl_sync(0xffffffffu, nm, j);
            float n1 = __shfl_sync(0xffffffffu, nm, j + 1);
            float n2 = __shfl_sync(0xffffffffu, nm, j + 2);
            float n3 = __shfl_sync(0xffffffffu, nm, j + 3);
            float2 v0 = H2[s0 * 32 + lane];
            float2 v1 = H2[s1 * 32 + lane];
            float2 v2 = H2[s2 * 32 + lane];
            float2 v3 = H2[s3 * 32 + lane];
            ax = fmaf(n0, v0.x, ax); ay = fmaf(n0, v0.y, ay);
            ax = fmaf(n1, v1.x, ax); ay = fmaf(n1, v1.y, ay);
            ax = fmaf(n2, v2.x, ax); ay = fmaf(n2, v2.y, ay);
            ax = fmaf(n3, v3.x, ax); ay = fmaf(n3, v3.y, ay);
        }
        for (; j < m; j++) {
            int sj = __shfl_sync(0xffffffffu, s, j);
            float nj = __shfl_sync(0xffffffffu, nm, j);
            float2 v = H2[sj * 32 + lane];
            ax = fmaf(nj, v.x, ax); ay = fmaf(nj, v.y, ay);
        }
    }
    float2 bb = ((const float2*)b)[lane];
    float2 o;
    o.x = fmaxf(ax + bb.x, 0.f);
    o.y = fmaxf(ay + bb.y, 0.f);
    ((float2*)g_x)[d * 32 + lane] = o;
}

// ---------------- GAT pull aggregation (warp/node) ----------------
__global__ void k_gat_agg(const float* __restrict__ b, int n) {
    int gt = blockIdx.x * blockDim.x + threadIdx.x;
    int d = gt >> 5, lane = gt & 31;
    if (d >= n) return;
    const float2* H2 = (const float2*)g_h;
    float ad_d = g_ad[d];
    float e0 = g_as[d] + ad_d;
    float l0 = e0 > 0.f ? e0 : 0.2f * e0;
    float wself = __expf(l0);
    float2 hd = H2[d * 32 + lane];
    float ax = wself * hd.x, ay = wself * hd.y;
    float zp = (lane == 0) ? wself : 0.f;
    int beg = g_rs[d], cnt = g_cnt[d];
    for (int c0 = 0; c0 < cnt; c0 += 32) {
        int idx = c0 + lane;
        int s = 0; float w = 0.f;
        if (idx < cnt) {
            s = __ldg(&g_csrc[beg + idx]);
            float ev = g_as[s] + ad_d;
            float lr = ev > 0.f ? ev : 0.2f * ev;
            w = __expf(lr);
        }
        zp += w;
        int m = min(32, cnt - c0);
        int j = 0;
        for (; j + 4 <= m; j += 4) {
            int s0 = __shfl_sync(0xffffffffu, s, j);
            int s1 = __shfl_sync(0xffffffffu, s, j + 1);
            int s2 = __shfl_sync(0xffffffffu, s, j + 2);
            int s3 = __shfl_sync(0xffffffffu, s, j + 3);
            float w0 = __shfl_sync(0xffffffffu, w, j);
            float w1 = __shfl_sync(0xffffffffu, w, j + 1);
            float w2 = __shfl_sync(0xffffffffu, w, j + 2);
            float w3 = __shfl_sync(0xffffffffu, w, j + 3);
            float2 v0 = H2[s0 * 32 + lane];
            float2 v1 = H2[s1 * 32 + lane];
            float2 v2 = H2[s2 * 32 + lane];
            float2 v3 = H2[s3 * 32 + lane];
            ax = fmaf(w0, v0.x, ax); ay = fmaf(w0, v0.y, ay);
            ax = fmaf(w1, v1.x, ax); ay = fmaf(w1, v1.y, ay);
            ax = fmaf(w2, v2.x, ax); ay = fmaf(w2, v2.y, ay);
            ax = fmaf(w3, v3.x, ax); ay = fmaf(w3, v3.y, ay);
        }
        for (; j < m; j++) {
            int sj = __shfl_sync(0xffffffffu, s, j);
            float wj = __shfl_sync(0xffffffffu, w, j);
            float2 v = H2[sj * 32 + lane];
            ax = fmaf(wj, v.x, ax); ay = fmaf(wj, v.y, ay);
        }
    }
#pragma unroll
    for (int o = 16; o; o >>= 1) zp += __shfl_xor_sync(0xffffffffu, zp, o);
    float inv = 1.0f / zp;
    float2 bb = ((const float2*)b)[lane];
    float2 o2;
    o2.x = fmaxf(fmaf(ax, inv, bb.x), 0.f);
    o2.y = fmaxf(fmaf(ay, inv, bb.y), 0.f);
    ((float2*)g_x)[d * 32 + lane] = o2;
}

// ================= fused gate + residual + speed head =================
__global__ void __launch_bounds__(256, 2)
k_final(const float* __restrict__ H,
        const float* __restrict__ gate_W, const float* __restrict__ gate_b,
        const float* __restrict__ res_W1, const float* __restrict__ res_b1,
        const float* __restrict__ res_W2, const float* __restrict__ res_b2,
        const float* __restrict__ sp_W1, const float* __restrict__ sp_b1,
        const float* __restrict__ sp_W2, const float* __restrict__ sp_b2,
        float* __restrict__ delta_out, float* __restrict__ hf_out,
        float* __restrict__ pred_out, int n) {
    extern __shared__ float sm[];
    float* fusT = sm;                        // 16640
    float4* Wb  = (float4*)(sm + 16640);     // 2048 float4

    int tid = threadIdx.x;
    int c4 = tid & 15, rp = tid >> 4;
    int row0 = blockIdx.x * 128;

    for (int i = tid; i < 4096; i += 256) {
        int rr = i & 127, j = i >> 7;
        int gr = row0 + rr;
        float4 v = make_float4(0.f, 0.f, 0.f, 0.f);
        if (gr < n) v = (j < 16) ? ((const float4*)H)[gr * 16 + j]
                                 : ((const float4*)g_x)[gr * 16 + (j - 16)];
        fusT[(j * 4 + 0) * STRIDE + rr] = v.x;
        fusT[(j * 4 + 1) * STRIDE + rr] = v.y;
        fusT[(j * 4 + 2) * STRIDE + rr] = v.z;
        fusT[(j * 4 + 3) * STRIDE + rr] = v.w;
    }
    for (int i = tid; i < 2048; i += 256) Wb[i] = ((const float4*)gate_W)[i];
    __syncthreads();

    u64 ga[4][4];
    {
        float4 b4 = ((const float4*)gate_b)[c4];
        u64 i0 = pack2(b4.x, b4.x), i1 = pack2(b4.y, b4.y);
        u64 i2 = pack2(b4.z, b4.z), i3 = pack2(b4.w, b4.w);
#pragma unroll
        for (int p = 0; p < 4; p++) { ga[p][0] = i0; ga[p][1] = i1; ga[p][2] = i2; ga[p][3] = i3; }
    }
#pragma unroll 4
    for (int k = 0; k < 128; k++) {
        float4 w = Wb[k * 16 + c4];
        u64 w0 = pack2(w.x, w.x), w1 = pack2(w.y, w.y);
        u64 w2 = pack2(w.z, w.z), w3 = pack2(w.w, w.w);
#pragma unroll
        for (int p = 0; p < 4; p++) {
            u64 x = *(const u64*)&fusT[k * STRIDE + 2 * rp + 32 * p];
            fma2(ga[p][0], x, w0); fma2(ga[p][1], x, w1);
            fma2(ga[p][2], x, w2); fma2(ga[p][3], x, w3);
        }
    }
    __syncthreads();
    for (int i = tid; i < 2048; i += 256) Wb[i] = ((const float4*)res_W1)[i];
    __syncthreads();

    u64 ra[4][4];
    {
        float4 b4 = ((const float4*)res_b1)[c4];
        u64 i0 = pack2(b4.x, b4.x), i1 = pack2(b4.y, b4.y);
        u64 i2 = pack2(b4.z, b4.z), i3 = pack2(b4.w, b4.w);
#pragma unroll
        for (int p = 0; p < 4; p++) { ra[p][0] = i0; ra[p][1] = i1; ra[p][2] = i2; ra[p][3] = i3; }
    }
#pragma unroll 4
    for (int k = 0; k < 128; k++) {
        float4 w = Wb[k * 16 + c4];
        u64 w0 = pack2(w.x, w.x), w1 = pack2(w.y, w.y);
        u64 w2 = pack2(w.z, w.z), w3 = pack2(w.w, w.w);
#pragma unroll
        for (int p = 0; p < 4; p++) {
            u64 x = *(const u64*)&fusT[k * STRIDE + 2 * rp + 32 * p];
            fma2(ra[p][0], x, w0); fma2(ra[p][1], x, w1);
            fma2(ra[p][2], x, w2); fma2(ra[p][3], x, w3);
        }
    }
    __syncthreads();
#pragma unroll
    for (int p = 0; p < 4; p++)
#pragma unroll
        for (int c = 0; c < 4; c++) {
            float2 v = unpack2(ra[p][c]);
            *(u64*)&fusT[(64 + c4 * 4 + c) * STRIDE + 2 * rp + 32 * p] =
                pack2(fmaxf(v.x, 0.f), fmaxf(v.y, 0.f));
        }
    // load res_W2 into Wb[0..1023] AND prefetch sp_W1 into Wb[1024..1535]
    for (int i = tid; i < 1024; i += 256) Wb[i] = ((const float4*)res_W2)[i];
    for (int i = tid; i < 512; i += 256) Wb[1024 + i] = ((const float4*)sp_W1)[i];
    __syncthreads();

    {
        float4 b4 = ((const float4*)res_b2)[c4];
        u64 i0 = pack2(b4.x, b4.x), i1 = pack2(b4.y, b4.y);
        u64 i2 = pack2(b4.z, b4.z), i3 = pack2(b4.w, b4.w);
#pragma unroll
        for (int p = 0; p < 4; p++) { ra[p][0] = i0; ra[p][1] = i1; ra[p][2] = i2; ra[p][3] = i3; }
    }
#pragma unroll 4
    for (int k = 0; k < 64; k++) {
        float4 w = Wb[k * 16 + c4];
        u64 w0 = pack2(w.x, w.x), w1 = pack2(w.y, w.y);
        u64 w2 = pack2(w.z, w.z), w3 = pack2(w.w, w.w);
#pragma unroll
        for (int p = 0; p < 4; p++) {
            u64 x = *(const u64*)&fusT[(64 + k) * STRIDE + 2 * rp + 32 * p];
            fma2(ra[p][0], x, w0); fma2(ra[p][1], x, w1);
            fma2(ra[p][2], x, w2); fma2(ra[p][3], x, w3);
        }
    }
    __syncthreads();

#pragma unroll
    for (int p = 0; p < 4; p++) {
        int r0 = 2 * rp + 32 * p;
        float d_[4][2], hf_[4][2];
#pragma unroll
        for (int c = 0; c < 4; c++) {
            float2 rv = unpack2(ra[p][c]);
            float2 gvv = unpack2(ga[p][c]);
            float2 hv = unpack2(*(const u64*)&fusT[(c4 * 4 + c) * STRIDE + r0]);
            d_[c][0] = sigmoidf_(gvv.x) * rv.x;
            d_[c][1] = sigmoidf_(gvv.y) * rv.y;
            hf_[c][0] = hv.x + d_[c][0];
            hf_[c][1] = hv.y + d_[c][1];
            *(u64*)&fusT[(64 + c4 * 4 + c) * STRIDE + r0] = pack2(hf_[c][0], hf_[c][1]);
        }
#pragma unroll
        for (int e = 0; e < 2; e++) {
            int row = row0 + r0 + e;
            if (row < n) {
                ((float4*)delta_out)[row * 16 + c4] =
                    make_float4(d_[0][e], d_[1][e], d_[2][e], d_[3][e]);
                ((float4*)hf_out)[row * 16 + c4] =
                    make_float4(hf_[0][e], hf_[1][e], hf_[2][e], hf_[3][e]);
            }
        }
    }
    __syncthreads();  // H_finalT written; sp_W1 already resident at Wb+1024

    float* tb = sm;  // reuse H region (cols 0..32): 128 rows x stride 33
    {
        u64 sa[4][2];
        float2 bb = ((const float2*)sp_b1)[c4];
        u64 i0 = pack2(bb.x, bb.x), i1 = pack2(bb.y, bb.y);
#pragma unroll
        for (int p = 0; p < 4; p++) { sa[p][0] = i0; sa[p][1] = i1; }
        const float2* spw = (const float2*)(Wb + 1024);
#pragma unroll 4
        for (int k = 0; k < 64; k++) {
            float2 wv = spw[k * 16 + c4];
            u64 w0 = pack2(wv.x, wv.x), w1 = pack2(wv.y, wv.y);
#pragma unroll
            for (int p = 0; p < 4; p++) {
                u64 x = *(const u64*)&fusT[(64 + k) * STRIDE + 2 * rp + 32 * p];
                fma2(sa[p][0], x, w0); fma2(sa[p][1], x, w1);
            }
        }
        __syncthreads();  // H-region reads (delta step) complete; safe to reuse as tb
#pragma unroll
        for (int p = 0; p < 4; p++) {
            int r0 = 2 * rp + 32 * p;
#pragma unroll
            for (int c = 0; c < 2; c++) {
                float2 v = unpack2(sa[p][c]);
                tb[(r0 + 0) * 33 + c4 * 2 + c] = fmaxf(v.x, 0.f);
                tb[(r0 + 1) * 33 + c4 * 2 + c] = fmaxf(v.y, 0.f);
            }
        }
    }
    __syncthreads();
    if (tid < 128) {
        int gr = row0 + tid;
        if (gr < n) {
            float acc = sp_b2[0];
#pragma unroll
            for (int k = 0; k < 32; k++) acc = fmaf(tb[tid * 33 + k], __ldg(&sp_W2[k]), acc);
            pred_out[gr] = acc;
        }
    }
}

// ---------------- launch ----------------
extern "C" void kernel_launch(void* const* d_in, const int* in_sizes, int n_in,
                              void* d_out, int out_size) {
    const float* H      = (const float*)d_in[0];
    const float* ev     = (const float*)d_in[1];
    const int*   ei     = (const int*)d_in[2];
    const float* enc_W1 = (const float*)d_in[3];
    const float* enc_b1 = (const float*)d_in[4];
    const float* enc_W2 = (const float*)d_in[5];
    const float* enc_b2 = (const float*)d_in[6];
    const float* gcn_W  = (const float*)d_in[7];
    const float* gcn_b  = (const float*)d_in[8];
    const float* gat_W  = (const float*)d_in[9];
    const float* att_s  = (const float*)d_in[10];
    const float* att_d  = (const float*)d_in[11];
    const float* gat_b  = (const float*)d_in[12];
    const float* gate_W = (const float*)d_in[13];
    const float* gate_b = (const float*)d_in[14];
    const float* res_W1 = (const float*)d_in[15];
    const float* res_b1 = (const float*)d_in[16];
    const float* res_W2 = (const float*)d_in[17];
    const float* res_b2 = (const float*)d_in[18];
    const float* sp_W1  = (const float*)d_in[19];
    const float* sp_b1  = (const float*)d_in[20];
    const float* sp_W2  = (const float*)d_in[21];
    const float* sp_b2  = (const float*)d_in[22];

    int n = in_sizes[0] / 64;
    int E = in_sizes[2] / 2;

    float* delta = (float*)d_out;
    float* hf    = delta + (size_t)n * 64;
    float* pred  = hf + (size_t)n * 64;

    int nb128  = (n + 127) / 128;
    int nb1024 = (n + 1023) / 1024;
    int nbW    = (n * 32 + 255) / 256;
    int E4     = E >> 2;
    int nbE4   = (E4 + (E & 3) + 255) / 256;

    const int ENC_SMEM = (1040 + 8320) * 4 + 1024 * 16;  // 53824
    const int GAT_SMEM = 8320 * 4 + 1024 * 16;           // 49664
    const int FIN_SMEM = 16640 * 4 + 2048 * 16;          // 99328

    static cudaStream_t s2 = nullptr;
    static cudaEvent_t evFork = nullptr, evJoin = nullptr;
    static void* cnt_ptr = nullptr;
    if (!s2) {
        cudaStreamCreate(&s2);
        cudaEventCreateWithFlags(&evFork, cudaEventDisableTiming);
        cudaEventCreateWithFlags(&evJoin, cudaEventDisableTiming);
        cudaGetSymbolAddress(&cnt_ptr, g_cnt);
        cudaFuncSetAttribute(k_encgemm, cudaFuncAttributeMaxDynamicSharedMemorySize, ENC_SMEM);
        cudaFuncSetAttribute(k_gemm_gat, cudaFuncAttributeMaxDynamicSharedMemorySize, GAT_SMEM);
        cudaFuncSetAttribute(k_final, cudaFuncAttributeMaxDynamicSharedMemorySize, FIN_SMEM);
    }

    // fork: encoder GEMM chain on s2, CSR build on main (default) stream
    cudaEventRecord(evFork, 0);
    cudaStreamWaitEvent(s2, evFork, 0);
    k_encgemm<<<nb128, 256, ENC_SMEM, s2>>>(ev, enc_W1, enc_b1, enc_W2, enc_b2, gcn_W, n);
    cudaEventRecord(evJoin, s2);

    cudaMemsetAsync(cnt_ptr, 0, (size_t)n * sizeof(int), 0);
    k_cnt<<<nbE4, 256>>>(ei, E);
    k_scanA<<<nb1024, 1024>>>(n);
    k_scanC2<<<nb1024, 1024>>>(n);
    k_csr<<<nbE4, 256>>>(ei, E);

    // join: aggregation needs both h (s2) and CSR (main)
    cudaStreamWaitEvent(0, evJoin, 0);
    k_gcn_agg<<<nbW, 256>>>(gcn_b, n);
    k_gemm_gat<<<nb128, 256, GAT_SMEM>>>(gat_W, att_s, att_d, n);
    k_gat_agg<<<nbW, 256>>>(gat_b, n);
    k_final<<<nb128, 256, FIN_SMEM>>>(H, gate_W, gate_b, res_W1, res_b1, res_W2, res_b2,
                                      sp_W1, sp_b1, sp_W2, sp_b2, delta, hf, pred, n);
}